// round 1
// baseline (speedup 1.0000x reference)
#include <cuda_runtime.h>

// Problem constants (from reference): B=4, N=256, M=256, D=64.
// One CTA per (b,i) tile of shape [M=256, D=64]. 256 threads; thread a owns row a.

__device__ __forceinline__ void ffma2(float& d0, float& d1,
                                      float a0, float a1,
                                      float b0, float b1)
{
    // d = a*b + d, two fp32 lanes packed (Blackwell FFMA2). Exact FMA rounding.
    asm("{\n\t"
        ".reg .b64 ra, rb, rc;\n\t"
        "mov.b64 ra, {%2, %3};\n\t"
        "mov.b64 rb, {%4, %5};\n\t"
        "mov.b64 rc, {%0, %1};\n\t"
        "fma.rn.f32x2 rc, ra, rb, rc;\n\t"
        "mov.b64 {%0, %1}, rc;\n\t"
        "}"
        : "+f"(d0), "+f"(d1)
        : "f"(a0), "f"(a1), "f"(b0), "f"(b1));
}

// acc[f] = bias[f] + sum_e inr[e] * wsT[e][f]   (wsT is 64x64 in smem, row e contiguous in f)
__device__ __forceinline__ void gemm_row(const float* inr, const float* ws,
                                         const float* __restrict__ bias, float* acc)
{
    #pragma unroll
    for (int f = 0; f < 64; f++) acc[f] = __ldg(bias + f);
    #pragma unroll 2
    for (int e = 0; e < 64; e++) {
        float xe = inr[e];
        const float4* w4 = (const float4*)(ws + e * 64);
        #pragma unroll
        for (int f = 0; f < 64; f += 8) {
            float4 wa = w4[f / 4];
            float4 wb = w4[f / 4 + 1];
            ffma2(acc[f + 0], acc[f + 1], xe, xe, wa.x, wa.y);
            ffma2(acc[f + 2], acc[f + 3], xe, xe, wa.z, wa.w);
            ffma2(acc[f + 4], acc[f + 5], xe, xe, wb.x, wb.y);
            ffma2(acc[f + 6], acc[f + 7], xe, xe, wb.z, wb.w);
        }
    }
}

// Load W^T into ws: ws[e*64+f] = W[f*64+e]. Coalesced global read.
__device__ __forceinline__ void load_wt(const float* __restrict__ W, float* ws, int tid)
{
    #pragma unroll
    for (int i = 0; i < 16; i++) {
        int idx = tid + 256 * i;          // idx = f*64 + e
        ws[(idx & 63) * 64 + (idx >> 6)] = W[idx];
    }
}

__global__ void __launch_bounds__(256, 1)
pair_attn_kernel(const float* __restrict__ x_all,
                 const float* __restrict__ Wq, const float* __restrict__ bq,
                 const float* __restrict__ Wk, const float* __restrict__ bk,
                 const float* __restrict__ Wv, const float* __restrict__ bv,
                 const float* __restrict__ Wo, const float* __restrict__ bo,
                 const float* __restrict__ lng, const float* __restrict__ lnb,
                 float* __restrict__ out_all)
{
    extern __shared__ float sm[];
    float* xs = sm;            // [256][64]
    float* qs = sm + 16384;    // [256][64]
    float* vs = sm + 32768;    // [256][64]
    float* ws = sm + 49152;    // [64][64] transposed weight scratch

    const int tid = threadIdx.x;
    const float* xg = x_all + (size_t)blockIdx.x * 16384;
    float* og       = out_all + (size_t)blockIdx.x * 16384;

    // ---- load x tile (coalesced float4) ----
    {
        const float4* src = (const float4*)xg;
        float4* dst = (float4*)xs;
        #pragma unroll
        for (int i = 0; i < 16; i++) dst[tid + 256 * i] = src[tid + 256 * i];
    }
    __syncthreads();

    // ---- own x row into registers ----
    float xr[64];
    {
        const float4* xrow = ((const float4*)xs) + tid * 16;
        #pragma unroll
        for (int i = 0; i < 16; i++) {
            float4 t = xrow[i];
            xr[4 * i + 0] = t.x; xr[4 * i + 1] = t.y;
            xr[4 * i + 2] = t.z; xr[4 * i + 3] = t.w;
        }
    }

    // ---- Q projection -> smem ----
    load_wt(Wq, ws, tid);
    __syncthreads();
    {
        float acc[64];
        gemm_row(xr, ws, bq, acc);
        float4* qrow = ((float4*)qs) + tid * 16;
        #pragma unroll
        for (int i = 0; i < 16; i++)
            qrow[i] = make_float4(acc[4*i], acc[4*i+1], acc[4*i+2], acc[4*i+3]);
    }
    __syncthreads();

    // ---- K projection -> registers ----
    load_wt(Wk, ws, tid);
    __syncthreads();
    float kacc[64];
    gemm_row(xr, ws, bk, kacc);
    __syncthreads();

    // ---- V projection -> smem ----
    load_wt(Wv, ws, tid);
    __syncthreads();
    {
        float acc[64];
        gemm_row(xr, ws, bv, acc);
        float4* vrow = ((float4*)vs) + tid * 16;
        #pragma unroll
        for (int i = 0; i < 16; i++)
            vrow[i] = make_float4(acc[4*i], acc[4*i+1], acc[4*i+2], acc[4*i+3]);
    }
    __syncthreads();

    // ---- fused scores/relu/normalize/context: single pass over c ----
    float ctx[64];
    #pragma unroll
    for (int d = 0; d < 64; d++) ctx[d] = 0.0f;
    float denom = 2.56e-10f;   // M * 1e-12, matches reference sum(probs + 1e-12)

    const float4* qs4 = (const float4*)qs;
    const float4* vs4 = (const float4*)vs;

    #pragma unroll 2
    for (int c = 0; c < 256; c++) {
        // s = k[a] . q[c]
        float c0x = 0.f, c0y = 0.f, c1x = 0.f, c1y = 0.f;
        float c2x = 0.f, c2y = 0.f, c3x = 0.f, c3y = 0.f;
        #pragma unroll
        for (int e = 0; e < 64; e += 8) {
            float4 qa = qs4[c * 16 + e / 4];
            float4 qb = qs4[c * 16 + e / 4 + 1];
            ffma2(c0x, c0y, kacc[e + 0], kacc[e + 1], qa.x, qa.y);
            ffma2(c1x, c1y, kacc[e + 2], kacc[e + 3], qa.z, qa.w);
            ffma2(c2x, c2y, kacc[e + 4], kacc[e + 5], qb.x, qb.y);
            ffma2(c3x, c3y, kacc[e + 6], kacc[e + 7], qb.z, qb.w);
        }
        float s = ((c0x + c0y) + (c1x + c1y)) + ((c2x + c2y) + (c3x + c3y));
        s *= 0.125f;                 // 1/sqrt(64)
        s = fmaxf(s, 0.0f);          // relu
        denom += s;
        // ctx += s * v[c]
        #pragma unroll
        for (int d = 0; d < 64; d += 8) {
            float4 va = vs4[c * 16 + d / 4];
            float4 vb = vs4[c * 16 + d / 4 + 1];
            ffma2(ctx[d + 0], ctx[d + 1], s, s, va.x, va.y);
            ffma2(ctx[d + 2], ctx[d + 3], s, s, va.z, va.w);
            ffma2(ctx[d + 4], ctx[d + 5], s, s, vb.x, vb.y);
            ffma2(ctx[d + 6], ctx[d + 7], s, s, vb.z, vb.w);
        }
    }
    {
        float inv = 1.0f / denom;
        #pragma unroll
        for (int d = 0; d < 64; d++) ctx[d] *= inv;
    }

    // ---- output projection ----
    __syncthreads();
    load_wt(Wo, ws, tid);
    __syncthreads();
    float y[64];
    gemm_row(ctx, ws, bo, y);

    // ---- residual (reload x row from smem) ----
    {
        const float4* xrow = ((const float4*)xs) + tid * 16;
        #pragma unroll
        for (int i = 0; i < 16; i++) {
            float4 t = xrow[i];
            y[4*i+0] += t.x; y[4*i+1] += t.y; y[4*i+2] += t.z; y[4*i+3] += t.w;
        }
    }

    // ---- LayerNorm over D=64 (two-pass, in registers) ----
    float mu = 0.0f;
    #pragma unroll
    for (int d = 0; d < 64; d++) mu += y[d];
    mu *= (1.0f / 64.0f);
    float var = 0.0f;
    #pragma unroll
    for (int d = 0; d < 64; d++) { float t = y[d] - mu; var += t * t; }
    var *= (1.0f / 64.0f);
    float rstd = rsqrtf(var + 1e-5f);

    // ---- scale/shift + store ----
    float4* o4 = ((float4*)og) + tid * 16;
    #pragma unroll
    for (int i = 0; i < 16; i++) {
        float4 r;
        r.x = (y[4*i+0] - mu) * rstd * __ldg(lng + 4*i+0) + __ldg(lnb + 4*i+0);
        r.y = (y[4*i+1] - mu) * rstd * __ldg(lng + 4*i+1) + __ldg(lnb + 4*i+1);
        r.z = (y[4*i+2] - mu) * rstd * __ldg(lng + 4*i+2) + __ldg(lnb + 4*i+2);
        r.w = (y[4*i+3] - mu) * rstd * __ldg(lng + 4*i+3) + __ldg(lnb + 4*i+3);
        o4[i] = r;
    }
}

extern "C" void kernel_launch(void* const* d_in, const int* in_sizes, int n_in,
                              void* d_out, int out_size)
{
    // metadata order:
    // 0 hidden_states (unused), 1 structure_matrix, 2 Wq, 3 bq, 4 Wk, 5 bk,
    // 6 Wv, 7 bv, 8 Wo, 9 bo, 10 ln_g, 11 ln_b
    const float* x   = (const float*)d_in[1];
    const float* Wq  = (const float*)d_in[2];
    const float* bq  = (const float*)d_in[3];
    const float* Wk  = (const float*)d_in[4];
    const float* bk  = (const float*)d_in[5];
    const float* Wv  = (const float*)d_in[6];
    const float* bv  = (const float*)d_in[7];
    const float* Wo  = (const float*)d_in[8];
    const float* bo  = (const float*)d_in[9];
    const float* lng = (const float*)d_in[10];
    const float* lnb = (const float*)d_in[11];
    float* out = (float*)d_out;

    int tiles = in_sizes[1] / (256 * 64);   // B*N = 1024
    size_t smem = 53248 * sizeof(float);    // 212992 bytes

    cudaFuncSetAttribute(pair_attn_kernel,
                         cudaFuncAttributeMaxDynamicSharedMemorySize, (int)smem);

    pair_attn_kernel<<<tiles, 256, smem>>>(x, Wq, bq, Wk, bk, Wv, bv, Wo, bo,
                                           lng, lnb, out);
}

// round 2
// speedup vs baseline: 13.8604x; 13.8604x over previous
#include <cuda_runtime.h>

// B=4, N=256, M=256, D=64. One CTA per (b,i) tile: [256 rows, 64 dim].
// 256 threads = 8 warps; warp w owns rows [32w, 32w+32) as two m16 tiles.
// All GEMMs via mma.sync.aligned.m16n8k8 tf32 with fp32 accumulate.

#define SQS 68   // Q smem stride (floats)
#define SVS 72   // V smem stride
#define SPS 68   // P / scratch smem stride
#define SWS 68   // weight smem stride

__device__ __forceinline__ unsigned f2tf(float x) {
    unsigned r; asm("cvt.rna.tf32.f32 %0, %1;" : "=r"(r) : "f"(x)); return r;
}
__device__ __forceinline__ float f2tff(float x) { return __uint_as_float(f2tf(x)); }
__device__ __forceinline__ unsigned fb(float x) { return __float_as_uint(x); }

__device__ __forceinline__ void mma8(float4& d, const unsigned a[4], unsigned b0, unsigned b1) {
    asm("mma.sync.aligned.m16n8k8.row.col.f32.tf32.tf32.f32 "
        "{%0,%1,%2,%3},{%4,%5,%6,%7},{%8,%9},{%0,%1,%2,%3};"
        : "+f"(d.x), "+f"(d.y), "+f"(d.z), "+f"(d.w)
        : "r"(a[0]), "r"(a[1]), "r"(a[2]), "r"(a[3]), "r"(b0), "r"(b1));
}

// Copy a 64x64 weight matrix (row-major) into sW with tf32 rounding.
__device__ __forceinline__ void loadW(const float* __restrict__ W, float* sW, int tid) {
    const float4* src = (const float4*)W;
    #pragma unroll
    for (int i = 0; i < 4; i++) {
        int idx = tid + 256 * i;
        float4 v = src[idx];
        *(float4*)&sW[(idx >> 4) * SWS + (idx & 15) * 4] =
            make_float4(f2tff(v.x), f2tff(v.y), f2tff(v.z), f2tff(v.w));
    }
}

// Load A-fragments for this warp's 32 rows from a row-major smem buffer.
__device__ __forceinline__ void loadA(unsigned a[2][8][4], const float* buf, int stride,
                                      int R0, int g, int t) {
    #pragma unroll
    for (int mt = 0; mt < 2; mt++)
        #pragma unroll
        for (int kt = 0; kt < 8; kt++) {
            int r = R0 + 16 * mt + g, c = 8 * kt + t;
            a[mt][kt][0] = fb(buf[r * stride + c]);
            a[mt][kt][1] = fb(buf[(r + 8) * stride + c]);
            a[mt][kt][2] = fb(buf[r * stride + c + 4]);
            a[mt][kt][3] = fb(buf[(r + 8) * stride + c + 4]);
        }
}

// C = X(frags) @ W^T + bias, tf32-rounded, written to dst rows owned by this warp.
__device__ __forceinline__ void project(const unsigned xa[2][8][4], const float* sW,
                                        const float* __restrict__ bias,
                                        float* dst, int stride, int R0, int g, int t) {
    #pragma unroll
    for (int nt = 0; nt < 8; nt++) {
        float4 a0 = make_float4(0.f, 0.f, 0.f, 0.f), a1 = a0;
        #pragma unroll
        for (int kt = 0; kt < 8; kt++) {
            unsigned b0 = fb(sW[(8 * nt + g) * SWS + 8 * kt + t]);
            unsigned b1 = fb(sW[(8 * nt + g) * SWS + 8 * kt + t + 4]);
            mma8(a0, xa[0][kt], b0, b1);
            mma8(a1, xa[1][kt], b0, b1);
        }
        float2 bb = __ldg((const float2*)&bias[8 * nt + 2 * t]);
        int c = 8 * nt + 2 * t;
        int r = R0 + g;
        *(float2*)&dst[r * stride + c]        = make_float2(f2tff(a0.x + bb.x), f2tff(a0.y + bb.y));
        *(float2*)&dst[(r + 8) * stride + c]  = make_float2(f2tff(a0.z + bb.x), f2tff(a0.w + bb.y));
        *(float2*)&dst[(r + 16) * stride + c] = make_float2(f2tff(a1.x + bb.x), f2tff(a1.y + bb.y));
        *(float2*)&dst[(r + 24) * stride + c] = make_float2(f2tff(a1.z + bb.x), f2tff(a1.w + bb.y));
    }
}

__global__ void __launch_bounds__(256, 1)
pair_attn_tc(const float* __restrict__ x_all,
             const float* __restrict__ Wq, const float* __restrict__ bq,
             const float* __restrict__ Wk, const float* __restrict__ bk,
             const float* __restrict__ Wv, const float* __restrict__ bv,
             const float* __restrict__ Wo, const float* __restrict__ bo,
             const float* __restrict__ lng, const float* __restrict__ lnb,
             float* __restrict__ out_all)
{
    extern __shared__ float smbuf[];
    float* sQ = smbuf;                 // 256*SQS
    float* sV = sQ + 256 * SQS;        // 256*SVS
    float* sP = sV + 256 * SVS;        // 256*SPS (x stage / K stage / P chunks / ctx stage)
    float* sW = sP + 256 * SPS;        // 64*SWS

    const int tid = threadIdx.x;
    const int lane = tid & 31;
    const int wrp = tid >> 5;
    const int g = lane >> 2;
    const int t = lane & 3;
    const int R0 = wrp * 32;

    const float* xg = x_all + (size_t)blockIdx.x * 16384;
    float* og = out_all + (size_t)blockIdx.x * 16384;

    // ---- stage x -> sP (tf32) and Wk -> sW ----
    {
        const float4* src = (const float4*)xg;
        #pragma unroll
        for (int i = 0; i < 16; i++) {
            int idx = tid + 256 * i;
            float4 v = src[idx];
            *(float4*)&sP[(idx >> 4) * SPS + (idx & 15) * 4] =
                make_float4(f2tff(v.x), f2tff(v.y), f2tff(v.z), f2tff(v.w));
        }
        loadW(Wk, sW, tid);
    }
    __syncthreads();

    // ---- x A-fragments (own rows) ----
    unsigned xa[2][8][4];
    loadA(xa, sP, SPS, R0, g, t);
    __syncwarp();   // all lanes done reading x rows before K overwrites them (warp-private rows)

    // ---- K projection -> sP (own rows), then K A-fragments ----
    project(xa, sW, bk, sP, SPS, R0, g, t);
    __syncwarp();
    unsigned ka[2][8][4];
    loadA(ka, sP, SPS, R0, g, t);

    // ---- Q projection -> sQ ----
    __syncthreads();            // everyone done with sW (Wk)
    loadW(Wq, sW, tid);
    __syncthreads();
    project(xa, sW, bq, sQ, SQS, R0, g, t);

    // ---- V projection -> sV ----
    __syncthreads();
    loadW(Wv, sW, tid);
    __syncthreads();
    project(xa, sW, bv, sV, SVS, R0, g, t);
    __syncthreads();            // sQ, sV fully visible

    // ---- mainloop: fused S -> relu -> unnormalized P -> ctx, 4 chunks of 64 cols ----
    float4 ctx[2][8];
    #pragma unroll
    for (int mt = 0; mt < 2; mt++)
        #pragma unroll
        for (int nt = 0; nt < 8; nt++) ctx[mt][nt] = make_float4(0.f, 0.f, 0.f, 0.f);
    float den[2][2] = {{0.f, 0.f}, {0.f, 0.f}};

    #pragma unroll 1
    for (int ch = 0; ch < 4; ch++) {
        const int c0 = ch * 64;
        #pragma unroll
        for (int nt = 0; nt < 8; nt++) {
            float4 s0 = make_float4(0.f, 0.f, 0.f, 0.f), s1 = s0;
            #pragma unroll
            for (int kt = 0; kt < 8; kt++) {
                unsigned b0 = fb(sQ[(c0 + 8 * nt + g) * SQS + 8 * kt + t]);
                unsigned b1 = fb(sQ[(c0 + 8 * nt + g) * SQS + 8 * kt + t + 4]);
                mma8(s0, ka[0][kt], b0, b1);
                mma8(s1, ka[1][kt], b0, b1);
            }
            const int c = 8 * nt + 2 * t;
            {
                float px = fmaxf(s0.x * 0.125f, 0.f), py = fmaxf(s0.y * 0.125f, 0.f);
                float pz = fmaxf(s0.z * 0.125f, 0.f), pw = fmaxf(s0.w * 0.125f, 0.f);
                den[0][0] += px + py; den[0][1] += pz + pw;
                int r = R0 + g;
                *(float2*)&sP[r * SPS + c]       = make_float2(f2tff(px), f2tff(py));
                *(float2*)&sP[(r + 8) * SPS + c] = make_float2(f2tff(pz), f2tff(pw));
            }
            {
                float px = fmaxf(s1.x * 0.125f, 0.f), py = fmaxf(s1.y * 0.125f, 0.f);
                float pz = fmaxf(s1.z * 0.125f, 0.f), pw = fmaxf(s1.w * 0.125f, 0.f);
                den[1][0] += px + py; den[1][1] += pz + pw;
                int r = R0 + 16 + g;
                *(float2*)&sP[r * SPS + c]       = make_float2(f2tff(px), f2tff(py));
                *(float2*)&sP[(r + 8) * SPS + c] = make_float2(f2tff(pz), f2tff(pw));
            }
        }
        __syncwarp();
        #pragma unroll
        for (int kt = 0; kt < 8; kt++) {
            unsigned pa[2][4];
            #pragma unroll
            for (int mt = 0; mt < 2; mt++) {
                int r = R0 + 16 * mt + g, c = 8 * kt + t;
                pa[mt][0] = fb(sP[r * SPS + c]);
                pa[mt][1] = fb(sP[(r + 8) * SPS + c]);
                pa[mt][2] = fb(sP[r * SPS + c + 4]);
                pa[mt][3] = fb(sP[(r + 8) * SPS + c + 4]);
            }
            #pragma unroll
            for (int nt = 0; nt < 8; nt++) {
                unsigned b0 = fb(sV[(c0 + 8 * kt + t) * SVS + 8 * nt + g]);
                unsigned b1 = fb(sV[(c0 + 8 * kt + t + 4) * SVS + 8 * nt + g]);
                mma8(ctx[0][nt], pa[0], b0, b1);
                mma8(ctx[1][nt], pa[1], b0, b1);
            }
        }
        __syncwarp();   // all lanes done reading P chunk before next chunk overwrites
    }

    // ---- normalize ctx rows: denom = sum(relu) + 256*1e-12 ----
    float inv[2][2];
    #pragma unroll
    for (int mt = 0; mt < 2; mt++)
        #pragma unroll
        for (int h = 0; h < 2; h++) {
            float d = den[mt][h];
            d += __shfl_xor_sync(0xffffffffu, d, 1);
            d += __shfl_xor_sync(0xffffffffu, d, 2);
            inv[mt][h] = 1.0f / (d + 2.56e-10f);
        }
    #pragma unroll
    for (int mt = 0; mt < 2; mt++)
        #pragma unroll
        for (int nt = 0; nt < 8; nt++) {
            ctx[mt][nt].x *= inv[mt][0]; ctx[mt][nt].y *= inv[mt][0];
            ctx[mt][nt].z *= inv[mt][1]; ctx[mt][nt].w *= inv[mt][1];
        }

    // ---- output projection: stage ctx -> sP, load Wo, mma ----
    loadW(Wo, sW, tid);   // safe: no warp reads sW during mainloop
    #pragma unroll
    for (int mt = 0; mt < 2; mt++)
        #pragma unroll
        for (int nt = 0; nt < 8; nt++) {
            int r = R0 + 16 * mt + g, c = 8 * nt + 2 * t;
            *(float2*)&sP[r * SPS + c]       = make_float2(f2tff(ctx[mt][nt].x), f2tff(ctx[mt][nt].y));
            *(float2*)&sP[(r + 8) * SPS + c] = make_float2(f2tff(ctx[mt][nt].z), f2tff(ctx[mt][nt].w));
        }
    __syncthreads();      // Wo visible everywhere; own sP rows trivially visible
    loadA(ka, sP, SPS, R0, g, t);   // reuse ka as ctx A-fragments

    float4 y[2][8];
    #pragma unroll
    for (int nt = 0; nt < 8; nt++) {
        float4 a0 = make_float4(0.f, 0.f, 0.f, 0.f), a1 = a0;
        #pragma unroll
        for (int kt = 0; kt < 8; kt++) {
            unsigned b0 = fb(sW[(8 * nt + g) * SWS + 8 * kt + t]);
            unsigned b1 = fb(sW[(8 * nt + g) * SWS + 8 * kt + t + 4]);
            mma8(a0, ka[0][kt], b0, b1);
            mma8(a1, ka[1][kt], b0, b1);
        }
        float2 bb = __ldg((const float2*)&bo[8 * nt + 2 * t]);
        y[0][nt] = make_float4(a0.x + bb.x, a0.y + bb.y, a0.z + bb.x, a0.w + bb.y);
        y[1][nt] = make_float4(a1.x + bb.x, a1.y + bb.y, a1.z + bb.x, a1.w + bb.y);
    }

    // ---- residual + LayerNorm + store ----
    #pragma unroll
    for (int mt = 0; mt < 2; mt++) {
        int r0 = R0 + 16 * mt + g, r1 = r0 + 8;
        float s0 = 0.f, s1 = 0.f, q0 = 0.f, q1 = 0.f;
        #pragma unroll
        for (int nt = 0; nt < 8; nt++) {
            int c = 8 * nt + 2 * t;
            float2 x0 = *(const float2*)&xg[r0 * 64 + c];
            float2 x1 = *(const float2*)&xg[r1 * 64 + c];
            y[mt][nt].x += x0.x; y[mt][nt].y += x0.y;
            y[mt][nt].z += x1.x; y[mt][nt].w += x1.y;
            s0 += y[mt][nt].x + y[mt][nt].y;
            q0 += y[mt][nt].x * y[mt][nt].x + y[mt][nt].y * y[mt][nt].y;
            s1 += y[mt][nt].z + y[mt][nt].w;
            q1 += y[mt][nt].z * y[mt][nt].z + y[mt][nt].w * y[mt][nt].w;
        }
        s0 += __shfl_xor_sync(0xffffffffu, s0, 1); s0 += __shfl_xor_sync(0xffffffffu, s0, 2);
        q0 += __shfl_xor_sync(0xffffffffu, q0, 1); q0 += __shfl_xor_sync(0xffffffffu, q0, 2);
        s1 += __shfl_xor_sync(0xffffffffu, s1, 1); s1 += __shfl_xor_sync(0xffffffffu, s1, 2);
        q1 += __shfl_xor_sync(0xffffffffu, q1, 1); q1 += __shfl_xor_sync(0xffffffffu, q1, 2);
        float mu0 = s0 * (1.f / 64.f), mu1 = s1 * (1.f / 64.f);
        float rs0 = rsqrtf(q0 * (1.f / 64.f) - mu0 * mu0 + 1e-5f);
        float rs1 = rsqrtf(q1 * (1.f / 64.f) - mu1 * mu1 + 1e-5f);
        #pragma unroll
        for (int nt = 0; nt < 8; nt++) {
            int c = 8 * nt + 2 * t;
            float2 gg = __ldg((const float2*)&lng[c]);
            float2 bb = __ldg((const float2*)&lnb[c]);
            float2 o0 = make_float2((y[mt][nt].x - mu0) * rs0 * gg.x + bb.x,
                                    (y[mt][nt].y - mu0) * rs0 * gg.y + bb.y);
            float2 o1 = make_float2((y[mt][nt].z - mu1) * rs1 * gg.x + bb.x,
                                    (y[mt][nt].w - mu1) * rs1 * gg.y + bb.y);
            *(float2*)&og[r0 * 64 + c] = o0;
            *(float2*)&og[r1 * 64 + c] = o1;
        }
    }
}

extern "C" void kernel_launch(void* const* d_in, const int* in_sizes, int n_in,
                              void* d_out, int out_size)
{
    const float* x   = (const float*)d_in[1];
    const float* Wq  = (const float*)d_in[2];
    const float* bq  = (const float*)d_in[3];
    const float* Wk  = (const float*)d_in[4];
    const float* bk  = (const float*)d_in[5];
    const float* Wv  = (const float*)d_in[6];
    const float* bv  = (const float*)d_in[7];
    const float* Wo  = (const float*)d_in[8];
    const float* bo  = (const float*)d_in[9];
    const float* lng = (const float*)d_in[10];
    const float* lnb = (const float*)d_in[11];
    float* out = (float*)d_out;

    int tiles = in_sizes[1] / (256 * 64);   // B*N = 1024
    size_t smem = (size_t)(256 * SQS + 256 * SVS + 256 * SPS + 64 * SWS) * sizeof(float); // 230400

    cudaFuncSetAttribute(pair_attn_tc,
                         cudaFuncAttributeMaxDynamicSharedMemorySize, (int)smem);

    pair_attn_tc<<<tiles, 256, smem>>>(x, Wq, bq, Wk, bk, Wv, bv, Wo, bo,
                                       lng, lnb, out);
}

// round 3
// speedup vs baseline: 21.1878x; 1.5287x over previous
#include <cuda_runtime.h>
#include <cuda_fp16.h>

// B=4, N=256, M=256, D=64. One CTA per (b,i) tile [256 rows, 64 dim].
// 512 threads = 16 warps; warp w owns rows [16w, 16w+16) as one m16 tile.
// All GEMMs: mma.sync.aligned.m16n8k16.row.col.f32.f16.f16.f32.
// Layout-matching trick: D-fragments (cols 2t,2t+1 per lane) pack directly into
// A-fragments (cols 2t,2t+1 / 2t+8,2t+9) -> K and P never round-trip through smem.

#define QS 72    // sQ row stride (halves)  -> 36 words, bank = 4g+t (conflict-free)
#define WS 72    // weight row stride (halves)
#define VS 264   // sVt row stride (halves) -> 132 words, bank = 4g+t (conflict-free)

__device__ __forceinline__ void mma16(float4& d, const unsigned a[4], unsigned b0, unsigned b1) {
    asm("mma.sync.aligned.m16n8k16.row.col.f32.f16.f16.f32 "
        "{%0,%1,%2,%3},{%4,%5,%6,%7},{%8,%9},{%0,%1,%2,%3};"
        : "+f"(d.x), "+f"(d.y), "+f"(d.z), "+f"(d.w)
        : "r"(a[0]), "r"(a[1]), "r"(a[2]), "r"(a[3]), "r"(b0), "r"(b1));
}

__device__ __forceinline__ unsigned pack2(float lo, float hi) {
    __half2 h = __floats2half2_rn(lo, hi);
    return *reinterpret_cast<unsigned*>(&h);
}

__global__ void __launch_bounds__(512, 1)
pair_attn_fp16(const float* __restrict__ x_all,
               const float* __restrict__ Wq, const float* __restrict__ bq,
               const float* __restrict__ Wk, const float* __restrict__ bk,
               const float* __restrict__ Wv, const float* __restrict__ bv,
               const float* __restrict__ Wo, const float* __restrict__ bo,
               const float* __restrict__ lng, const float* __restrict__ lnb,
               float* __restrict__ out_all)
{
    extern __shared__ __half sm[];
    __half* sQ  = sm;                    // [256][QS]   Q rows (scale 1/8 folded in)
    __half* sVt = sQ + 256 * QS;         // [64][VS]    V transposed: sVt[d][c]
    __half* sW  = sVt + 64 * VS;         // [4][64][WS] Wq,Wk,Wv,Wo as fp16

    const int tid  = threadIdx.x;
    const int lane = tid & 31;
    const int wrp  = tid >> 5;
    const int g    = lane >> 2;
    const int t    = lane & 3;
    const int R0   = wrp * 16;
    const int r0   = R0 + g, r1 = R0 + 8 + g;

    const float* xg = x_all  + (size_t)blockIdx.x * 16384;
    float*       og = out_all + (size_t)blockIdx.x * 16384;

    // ---- stage all 4 weights as fp16 (each thread: one 8-elem run of one row) ----
    {
        const float* Ws[4] = {Wq, Wk, Wv, Wo};
        const int f  = tid >> 3;          // row 0..63
        const int e0 = (tid & 7) * 8;     // col start
        #pragma unroll
        for (int w = 0; w < 4; w++) {
            float4 p0 = *(const float4*)(Ws[w] + f * 64 + e0);
            float4 p1 = *(const float4*)(Ws[w] + f * 64 + e0 + 4);
            unsigned u[4];
            u[0] = pack2(p0.x, p0.y); u[1] = pack2(p0.z, p0.w);
            u[2] = pack2(p1.x, p1.y); u[3] = pack2(p1.z, p1.w);
            *(uint4*)&sW[(w * 64 + f) * WS + e0] = *(uint4*)u;
        }
    }

    // ---- x A-fragments from gmem (own 16 rows) ----
    unsigned xa[4][4];
    #pragma unroll
    for (int kt = 0; kt < 4; kt++) {
        int c = 16 * kt + 2 * t;
        float2 v0 = *(const float2*)&xg[r0 * 64 + c];
        float2 v1 = *(const float2*)&xg[r1 * 64 + c];
        float2 v2 = *(const float2*)&xg[r0 * 64 + c + 8];
        float2 v3 = *(const float2*)&xg[r1 * 64 + c + 8];
        xa[kt][0] = pack2(v0.x, v0.y);
        xa[kt][1] = pack2(v1.x, v1.y);
        xa[kt][2] = pack2(v2.x, v2.y);
        xa[kt][3] = pack2(v3.x, v3.y);
    }
    __syncthreads();   // weights staged

    // ---- projections ----
    unsigned ka[4][4];                     // K A-fragments (register-resident)
    {
        float4 dq[8], dk[8], dv[8];
        #pragma unroll
        for (int nt = 0; nt < 8; nt++) {
            dq[nt] = make_float4(0.f, 0.f, 0.f, 0.f);
            dk[nt] = dq[nt]; dv[nt] = dq[nt];
        }
        #pragma unroll
        for (int nt = 0; nt < 8; nt++) {
            #pragma unroll
            for (int kt = 0; kt < 4; kt++) {
                int off = (8 * nt + g) * WS + 16 * kt + 2 * t;
                unsigned q0 = *(const unsigned*)&sW[0 * 64 * WS + off];
                unsigned q1 = *(const unsigned*)&sW[0 * 64 * WS + off + 8];
                mma16(dq[nt], xa[kt], q0, q1);
                unsigned k0 = *(const unsigned*)&sW[1 * 64 * WS + off];
                unsigned k1 = *(const unsigned*)&sW[1 * 64 * WS + off + 8];
                mma16(dk[nt], xa[kt], k0, k1);
                unsigned v0 = *(const unsigned*)&sW[2 * 64 * WS + off];
                unsigned v1 = *(const unsigned*)&sW[2 * 64 * WS + off + 8];
                mma16(dv[nt], xa[kt], v0, v1);
            }
        }
        #pragma unroll
        for (int nt = 0; nt < 8; nt++) {
            int c = 8 * nt + 2 * t;
            float2 bbq = __ldg((const float2*)&bq[c]);
            float2 bbk = __ldg((const float2*)&bk[c]);
            float2 bbv = __ldg((const float2*)&bv[c]);
            // Q: bias, fold 1/8 scale, store to sQ
            *(unsigned*)&sQ[r0 * QS + c] = pack2((dq[nt].x + bbq.x) * 0.125f,
                                                 (dq[nt].y + bbq.y) * 0.125f);
            *(unsigned*)&sQ[r1 * QS + c] = pack2((dq[nt].z + bbq.x) * 0.125f,
                                                 (dq[nt].w + bbq.y) * 0.125f);
            // V: bias, store transposed sVt[d][c]
            sVt[(c)     * VS + r0] = __float2half_rn(dv[nt].x + bbv.x);
            sVt[(c + 1) * VS + r0] = __float2half_rn(dv[nt].y + bbv.y);
            sVt[(c)     * VS + r1] = __float2half_rn(dv[nt].z + bbv.x);
            sVt[(c + 1) * VS + r1] = __float2half_rn(dv[nt].w + bbv.y);
            // K: bias, keep
            dk[nt].x += bbk.x; dk[nt].y += bbk.y; dk[nt].z += bbk.x; dk[nt].w += bbk.y;
        }
        // pack K D-fragments into A-fragments (layout match: nt-pair -> kt)
        #pragma unroll
        for (int kt = 0; kt < 4; kt++) {
            ka[kt][0] = pack2(dk[2*kt].x,   dk[2*kt].y);
            ka[kt][1] = pack2(dk[2*kt].z,   dk[2*kt].w);
            ka[kt][2] = pack2(dk[2*kt+1].x, dk[2*kt+1].y);
            ka[kt][3] = pack2(dk[2*kt+1].z, dk[2*kt+1].w);
        }
    }
    __syncthreads();   // sQ, sVt complete

    // ---- mainloop: S -> relu -> pack -> PV, 16 c-blocks of 16 ----
    float4 ctx[8];
    #pragma unroll
    for (int nt = 0; nt < 8; nt++) ctx[nt] = make_float4(0.f, 0.f, 0.f, 0.f);
    float den0 = 0.f, den1 = 0.f;

    #pragma unroll 2
    for (int cb = 0; cb < 16; cb++) {
        float4 se = make_float4(0.f, 0.f, 0.f, 0.f), so = se;
        #pragma unroll
        for (int kt = 0; kt < 4; kt++) {
            int off = 16 * kt + 2 * t;
            unsigned qe0 = *(const unsigned*)&sQ[(16 * cb + g)     * QS + off];
            unsigned qe1 = *(const unsigned*)&sQ[(16 * cb + g)     * QS + off + 8];
            unsigned qo0 = *(const unsigned*)&sQ[(16 * cb + 8 + g) * QS + off];
            unsigned qo1 = *(const unsigned*)&sQ[(16 * cb + 8 + g) * QS + off + 8];
            mma16(se, ka[kt], qe0, qe1);
            mma16(so, ka[kt], qo0, qo1);
        }
        // relu (scale folded into Q already)
        se.x = fmaxf(se.x, 0.f); se.y = fmaxf(se.y, 0.f);
        se.z = fmaxf(se.z, 0.f); se.w = fmaxf(se.w, 0.f);
        so.x = fmaxf(so.x, 0.f); so.y = fmaxf(so.y, 0.f);
        so.z = fmaxf(so.z, 0.f); so.w = fmaxf(so.w, 0.f);
        den0 += (se.x + se.y) + (so.x + so.y);
        den1 += (se.z + se.w) + (so.z + so.w);
        unsigned pa[4];
        pa[0] = pack2(se.x, se.y); pa[1] = pack2(se.z, se.w);
        pa[2] = pack2(so.x, so.y); pa[3] = pack2(so.z, so.w);
        #pragma unroll
        for (int nt = 0; nt < 8; nt++) {
            unsigned v0 = *(const unsigned*)&sVt[(8 * nt + g) * VS + 16 * cb + 2 * t];
            unsigned v1 = *(const unsigned*)&sVt[(8 * nt + g) * VS + 16 * cb + 2 * t + 8];
            mma16(ctx[nt], pa, v0, v1);
        }
    }

    // ---- normalize: denom = sum(relu) + 256e-12 ----
    den0 += __shfl_xor_sync(0xffffffffu, den0, 1);
    den0 += __shfl_xor_sync(0xffffffffu, den0, 2);
    den1 += __shfl_xor_sync(0xffffffffu, den1, 1);
    den1 += __shfl_xor_sync(0xffffffffu, den1, 2);
    float inv0 = 1.0f / (den0 + 2.56e-10f);
    float inv1 = 1.0f / (den1 + 2.56e-10f);
    #pragma unroll
    for (int nt = 0; nt < 8; nt++) {
        ctx[nt].x *= inv0; ctx[nt].y *= inv0;
        ctx[nt].z *= inv1; ctx[nt].w *= inv1;
    }

    // ---- output projection (ctx D-frags -> A-frags in registers) ----
    unsigned co[4][4];
    #pragma unroll
    for (int kt = 0; kt < 4; kt++) {
        co[kt][0] = pack2(ctx[2*kt].x,   ctx[2*kt].y);
        co[kt][1] = pack2(ctx[2*kt].z,   ctx[2*kt].w);
        co[kt][2] = pack2(ctx[2*kt+1].x, ctx[2*kt+1].y);
        co[kt][3] = pack2(ctx[2*kt+1].z, ctx[2*kt+1].w);
    }
    float4 y[8];
    #pragma unroll
    for (int nt = 0; nt < 8; nt++) {
        y[nt] = make_float4(0.f, 0.f, 0.f, 0.f);
        #pragma unroll
        for (int kt = 0; kt < 4; kt++) {
            int off = (3 * 64 + 8 * nt + g) * WS + 16 * kt + 2 * t;
            unsigned b0 = *(const unsigned*)&sW[off];
            unsigned b1 = *(const unsigned*)&sW[off + 8];
            mma16(y[nt], co[kt], b0, b1);
        }
        float2 bb = __ldg((const float2*)&bo[8 * nt + 2 * t]);
        y[nt].x += bb.x; y[nt].y += bb.y; y[nt].z += bb.x; y[nt].w += bb.y;
    }

    // ---- residual + LayerNorm + store ----
    float s0 = 0.f, s1 = 0.f, q0 = 0.f, q1 = 0.f;
    #pragma unroll
    for (int nt = 0; nt < 8; nt++) {
        int c = 8 * nt + 2 * t;
        float2 x0 = *(const float2*)&xg[r0 * 64 + c];
        float2 x1 = *(const float2*)&xg[r1 * 64 + c];
        y[nt].x += x0.x; y[nt].y += x0.y;
        y[nt].z += x1.x; y[nt].w += x1.y;
        s0 += y[nt].x + y[nt].y;  q0 += y[nt].x * y[nt].x + y[nt].y * y[nt].y;
        s1 += y[nt].z + y[nt].w;  q1 += y[nt].z * y[nt].z + y[nt].w * y[nt].w;
    }
    s0 += __shfl_xor_sync(0xffffffffu, s0, 1); s0 += __shfl_xor_sync(0xffffffffu, s0, 2);
    q0 += __shfl_xor_sync(0xffffffffu, q0, 1); q0 += __shfl_xor_sync(0xffffffffu, q0, 2);
    s1 += __shfl_xor_sync(0xffffffffu, s1, 1); s1 += __shfl_xor_sync(0xffffffffu, s1, 2);
    q1 += __shfl_xor_sync(0xffffffffu, q1, 1); q1 += __shfl_xor_sync(0xffffffffu, q1, 2);
    float mu0 = s0 * (1.f / 64.f), mu1 = s1 * (1.f / 64.f);
    float rs0 = rsqrtf(q0 * (1.f / 64.f) - mu0 * mu0 + 1e-5f);
    float rs1 = rsqrtf(q1 * (1.f / 64.f) - mu1 * mu1 + 1e-5f);
    #pragma unroll
    for (int nt = 0; nt < 8; nt++) {
        int c = 8 * nt + 2 * t;
        float2 gg = __ldg((const float2*)&lng[c]);
        float2 bb = __ldg((const float2*)&lnb[c]);
        *(float2*)&og[r0 * 64 + c] = make_float2((y[nt].x - mu0) * rs0 * gg.x + bb.x,
                                                 (y[nt].y - mu0) * rs0 * gg.y + bb.y);
        *(float2*)&og[r1 * 64 + c] = make_float2((y[nt].z - mu1) * rs1 * gg.x + bb.x,
                                                 (y[nt].w - mu1) * rs1 * gg.y + bb.y);
    }
}

extern "C" void kernel_launch(void* const* d_in, const int* in_sizes, int n_in,
                              void* d_out, int out_size)
{
    const float* x   = (const float*)d_in[1];
    const float* Wq  = (const float*)d_in[2];
    const float* bq  = (const float*)d_in[3];
    const float* Wk  = (const float*)d_in[4];
    const float* bk  = (const float*)d_in[5];
    const float* Wv  = (const float*)d_in[6];
    const float* bv  = (const float*)d_in[7];
    const float* Wo  = (const float*)d_in[8];
    const float* bo  = (const float*)d_in[9];
    const float* lng = (const float*)d_in[10];
    const float* lnb = (const float*)d_in[11];
    float* out = (float*)d_out;

    int tiles = in_sizes[1] / (256 * 64);   // B*N = 1024
    size_t smem = (size_t)(256 * QS + 64 * VS + 4 * 64 * WS) * sizeof(__half); // 107520 B

    cudaFuncSetAttribute(pair_attn_fp16,
                         cudaFuncAttributeMaxDynamicSharedMemorySize, (int)smem);

    pair_attn_fp16<<<tiles, 512, smem>>>(x, Wq, bq, Wk, bk, Wv, bv, Wo, bo,
                                         lng, lnb, out);
}

// round 4
// speedup vs baseline: 25.1128x; 1.1852x over previous
#include <cuda_runtime.h>
#include <cuda_fp16.h>

// B=4, N=256, M=256, D=64. One CTA per (b,i) tile [256 rows, 64 dim].
// 256 threads = 8 warps; warp w owns rows [32w, 32w+32) as TWO m16 tiles.
// GEMMs: mma.sync.aligned.m16n8k16.row.col.f32.f16.f16.f32.
// B-operands via ldmatrix.x4; K and P stay register-resident (D->A layout match).

#define QS 72    // sQ row stride (halves): rows hit banks 4r+c -> LDSM conflict-free
#define WS 72    // weight row stride (halves)
#define VS 264   // sVt row stride (halves)

__device__ __forceinline__ void mma16(float4& d, const unsigned a[4], unsigned b0, unsigned b1) {
    asm("mma.sync.aligned.m16n8k16.row.col.f32.f16.f16.f32 "
        "{%0,%1,%2,%3},{%4,%5,%6,%7},{%8,%9},{%0,%1,%2,%3};"
        : "+f"(d.x), "+f"(d.y), "+f"(d.z), "+f"(d.w)
        : "r"(a[0]), "r"(a[1]), "r"(a[2]), "r"(a[3]), "r"(b0), "r"(b1));
}

__device__ __forceinline__ void ldsm4(unsigned& r0, unsigned& r1, unsigned& r2, unsigned& r3,
                                      const __half* p) {
    unsigned a = (unsigned)__cvta_generic_to_shared(p);
    asm volatile("ldmatrix.sync.aligned.m8n8.x4.shared.b16 {%0,%1,%2,%3},[%4];"
                 : "=r"(r0), "=r"(r1), "=r"(r2), "=r"(r3) : "r"(a));
}

__device__ __forceinline__ unsigned pack2(float lo, float hi) {
    __half2 h = __floats2half2_rn(lo, hi);
    return *reinterpret_cast<unsigned*>(&h);
}

__global__ void __launch_bounds__(256, 1)
pair_attn_v4(const float* __restrict__ x_all,
             const float* __restrict__ Wq, const float* __restrict__ bq,
             const float* __restrict__ Wk, const float* __restrict__ bk,
             const float* __restrict__ Wv, const float* __restrict__ bv,
             const float* __restrict__ Wo, const float* __restrict__ bo,
             const float* __restrict__ lng, const float* __restrict__ lnb,
             float* __restrict__ out_all)
{
    extern __shared__ __half sm[];
    __half* sQ  = sm;                    // [256][QS]  Q rows (1/8 scale folded)
    __half* sVt = sQ + 256 * QS;         // [64][VS]   V transposed: sVt[d][c]
    __half* sW  = sVt + 64 * VS;         // [4][64][WS]

    const int tid  = threadIdx.x;
    const int lane = tid & 31;
    const int wrp  = tid >> 5;
    const int g    = lane >> 2;
    const int t    = lane & 3;
    const int R0   = wrp * 32;
    // ldmatrix per-lane tile addressing: tile = lane/8; row-within = lane%8
    const int lro = ((lane >> 4) & 1) * 8 + (lane & 7);  // row offset (tiles 2,3 -> +8)
    const int lco = ((lane >> 3) & 1) * 8;               // col offset (tiles 1,3 -> +8)

    const float* xg = x_all   + (size_t)blockIdx.x * 16384;
    float*       og = out_all + (size_t)blockIdx.x * 16384;

    // ---- stage all 4 weights as fp16 (thread: row f, 16-col run) ----
    {
        const float* Wsrc[4] = {Wq, Wk, Wv, Wo};
        const int f  = tid >> 2;
        const int e0 = (tid & 3) * 16;
        #pragma unroll
        for (int w = 0; w < 4; w++) {
            const float* src = Wsrc[w] + f * 64 + e0;
            unsigned u[8];
            #pragma unroll
            for (int i = 0; i < 4; i++) {
                float4 p = *(const float4*)(src + 4 * i);
                u[2*i]   = pack2(p.x, p.y);
                u[2*i+1] = pack2(p.z, p.w);
            }
            *(uint4*)&sW[(w * 64 + f) * WS + e0]     = *(uint4*)&u[0];
            *(uint4*)&sW[(w * 64 + f) * WS + e0 + 8] = *(uint4*)&u[4];
        }
    }
    __syncthreads();

    // ---- projections, one m16 tile at a time (limits live registers) ----
    unsigned ka[2][4][4];
    #pragma unroll
    for (int mt = 0; mt < 2; mt++) {
        const int rA = R0 + 16 * mt + g, rB = rA + 8;
        // x A-fragments from gmem
        unsigned xa[4][4];
        #pragma unroll
        for (int kt = 0; kt < 4; kt++) {
            int c = 16 * kt + 2 * t;
            float2 v0 = *(const float2*)&xg[rA * 64 + c];
            float2 v1 = *(const float2*)&xg[rB * 64 + c];
            float2 v2 = *(const float2*)&xg[rA * 64 + c + 8];
            float2 v3 = *(const float2*)&xg[rB * 64 + c + 8];
            xa[kt][0] = pack2(v0.x, v0.y);
            xa[kt][1] = pack2(v1.x, v1.y);
            xa[kt][2] = pack2(v2.x, v2.y);
            xa[kt][3] = pack2(v3.x, v3.y);
        }
        float4 dq[8], dk[8], dv[8];
        #pragma unroll
        for (int nt = 0; nt < 8; nt++) {
            dq[nt] = make_float4(0.f, 0.f, 0.f, 0.f);
            dk[nt] = dq[nt]; dv[nt] = dq[nt];
        }
        #pragma unroll
        for (int kt = 0; kt < 4; kt++) {
            #pragma unroll
            for (int j = 0; j < 4; j++) {   // nt pair (2j, 2j+1)
                unsigned b0, b1, b2, b3;
                ldsm4(b0, b1, b2, b3, &sW[(0 * 64 + 16 * j + lro) * WS + 16 * kt + lco]);
                mma16(dq[2*j],   xa[kt], b0, b1);
                mma16(dq[2*j+1], xa[kt], b2, b3);
                ldsm4(b0, b1, b2, b3, &sW[(1 * 64 + 16 * j + lro) * WS + 16 * kt + lco]);
                mma16(dk[2*j],   xa[kt], b0, b1);
                mma16(dk[2*j+1], xa[kt], b2, b3);
                ldsm4(b0, b1, b2, b3, &sW[(2 * 64 + 16 * j + lro) * WS + 16 * kt + lco]);
                mma16(dv[2*j],   xa[kt], b0, b1);
                mma16(dv[2*j+1], xa[kt], b2, b3);
            }
        }
        #pragma unroll
        for (int nt = 0; nt < 8; nt++) {
            int c = 8 * nt + 2 * t;
            float2 bbq = __ldg((const float2*)&bq[c]);
            float2 bbk = __ldg((const float2*)&bk[c]);
            float2 bbv = __ldg((const float2*)&bv[c]);
            *(unsigned*)&sQ[rA * QS + c] = pack2((dq[nt].x + bbq.x) * 0.125f,
                                                 (dq[nt].y + bbq.y) * 0.125f);
            *(unsigned*)&sQ[rB * QS + c] = pack2((dq[nt].z + bbq.x) * 0.125f,
                                                 (dq[nt].w + bbq.y) * 0.125f);
            sVt[(c)     * VS + rA] = __float2half_rn(dv[nt].x + bbv.x);
            sVt[(c + 1) * VS + rA] = __float2half_rn(dv[nt].y + bbv.y);
            sVt[(c)     * VS + rB] = __float2half_rn(dv[nt].z + bbv.x);
            sVt[(c + 1) * VS + rB] = __float2half_rn(dv[nt].w + bbv.y);
            dk[nt].x += bbk.x; dk[nt].y += bbk.y; dk[nt].z += bbk.x; dk[nt].w += bbk.y;
        }
        #pragma unroll
        for (int kt = 0; kt < 4; kt++) {
            ka[mt][kt][0] = pack2(dk[2*kt].x,   dk[2*kt].y);
            ka[mt][kt][1] = pack2(dk[2*kt].z,   dk[2*kt].w);
            ka[mt][kt][2] = pack2(dk[2*kt+1].x, dk[2*kt+1].y);
            ka[mt][kt][3] = pack2(dk[2*kt+1].z, dk[2*kt+1].w);
        }
    }
    __syncthreads();   // sQ, sVt complete

    // ---- mainloop: S -> relu -> pack -> PV over 16 c-blocks ----
    float4 ctx[2][8];
    #pragma unroll
    for (int mt = 0; mt < 2; mt++)
        #pragma unroll
        for (int nt = 0; nt < 8; nt++) ctx[mt][nt] = make_float4(0.f, 0.f, 0.f, 0.f);
    float den[2][2] = {{0.f, 0.f}, {0.f, 0.f}};

    #pragma unroll 2
    for (int cb = 0; cb < 16; cb++) {
        float4 s[2][2];
        s[0][0] = make_float4(0.f, 0.f, 0.f, 0.f);
        s[0][1] = s[0][0]; s[1][0] = s[0][0]; s[1][1] = s[0][0];
        #pragma unroll
        for (int kt = 0; kt < 4; kt++) {
            unsigned q0, q1, q2, q3;
            ldsm4(q0, q1, q2, q3, &sQ[(16 * cb + lro) * QS + 16 * kt + lco]);
            mma16(s[0][0], ka[0][kt], q0, q1);
            mma16(s[0][1], ka[0][kt], q2, q3);
            mma16(s[1][0], ka[1][kt], q0, q1);
            mma16(s[1][1], ka[1][kt], q2, q3);
        }
        unsigned pa[2][4];
        #pragma unroll
        for (int mt = 0; mt < 2; mt++) {
            float ex = fmaxf(s[mt][0].x, 0.f), ey = fmaxf(s[mt][0].y, 0.f);
            float ez = fmaxf(s[mt][0].z, 0.f), ew = fmaxf(s[mt][0].w, 0.f);
            float ox = fmaxf(s[mt][1].x, 0.f), oy = fmaxf(s[mt][1].y, 0.f);
            float oz = fmaxf(s[mt][1].z, 0.f), ow = fmaxf(s[mt][1].w, 0.f);
            den[mt][0] += (ex + ey) + (ox + oy);
            den[mt][1] += (ez + ew) + (oz + ow);
            pa[mt][0] = pack2(ex, ey); pa[mt][1] = pack2(ez, ew);
            pa[mt][2] = pack2(ox, oy); pa[mt][3] = pack2(oz, ow);
        }
        #pragma unroll
        for (int j = 0; j < 4; j++) {   // d-tile pair (2j, 2j+1)
            unsigned v0, v1, v2, v3;
            ldsm4(v0, v1, v2, v3, &sVt[(16 * j + lro) * VS + 16 * cb + lco]);
            mma16(ctx[0][2*j],   pa[0], v0, v1);
            mma16(ctx[0][2*j+1], pa[0], v2, v3);
            mma16(ctx[1][2*j],   pa[1], v0, v1);
            mma16(ctx[1][2*j+1], pa[1], v2, v3);
        }
    }

    // ---- normalize: denom = sum(relu) + 256e-12 ----
    float inv[2][2];
    #pragma unroll
    for (int mt = 0; mt < 2; mt++)
        #pragma unroll
        for (int h = 0; h < 2; h++) {
            float d = den[mt][h];
            d += __shfl_xor_sync(0xffffffffu, d, 1);
            d += __shfl_xor_sync(0xffffffffu, d, 2);
            inv[mt][h] = 1.0f / (d + 2.56e-10f);
        }
    unsigned cf[2][4][4];
    #pragma unroll
    for (int mt = 0; mt < 2; mt++) {
        #pragma unroll
        for (int nt = 0; nt < 8; nt++) {
            ctx[mt][nt].x *= inv[mt][0]; ctx[mt][nt].y *= inv[mt][0];
            ctx[mt][nt].z *= inv[mt][1]; ctx[mt][nt].w *= inv[mt][1];
        }
        #pragma unroll
        for (int kt = 0; kt < 4; kt++) {
            cf[mt][kt][0] = pack2(ctx[mt][2*kt].x,   ctx[mt][2*kt].y);
            cf[mt][kt][1] = pack2(ctx[mt][2*kt].z,   ctx[mt][2*kt].w);
            cf[mt][kt][2] = pack2(ctx[mt][2*kt+1].x, ctx[mt][2*kt+1].y);
            cf[mt][kt][3] = pack2(ctx[mt][2*kt+1].z, ctx[mt][2*kt+1].w);
        }
    }

    // ---- output projection ----
    float4 y[2][8];
    #pragma unroll
    for (int mt = 0; mt < 2; mt++)
        #pragma unroll
        for (int nt = 0; nt < 8; nt++) y[mt][nt] = make_float4(0.f, 0.f, 0.f, 0.f);
    #pragma unroll
    for (int kt = 0; kt < 4; kt++)
        #pragma unroll
        for (int j = 0; j < 4; j++) {
            unsigned b0, b1, b2, b3;
            ldsm4(b0, b1, b2, b3, &sW[(3 * 64 + 16 * j + lro) * WS + 16 * kt + lco]);
            mma16(y[0][2*j],   cf[0][kt], b0, b1);
            mma16(y[0][2*j+1], cf[0][kt], b2, b3);
            mma16(y[1][2*j],   cf[1][kt], b0, b1);
            mma16(y[1][2*j+1], cf[1][kt], b2, b3);
        }

    // ---- residual + LayerNorm + store, per m-tile ----
    #pragma unroll
    for (int mt = 0; mt < 2; mt++) {
        const int rA = R0 + 16 * mt + g, rB = rA + 8;
        float s0 = 0.f, s1 = 0.f, q0 = 0.f, q1 = 0.f;
        #pragma unroll
        for (int nt = 0; nt < 8; nt++) {
            int c = 8 * nt + 2 * t;
            float2 bb = __ldg((const float2*)&bo[c]);
            float2 x0 = *(const float2*)&xg[rA * 64 + c];
            float2 x1 = *(const float2*)&xg[rB * 64 + c];
            y[mt][nt].x += bb.x + x0.x; y[mt][nt].y += bb.y + x0.y;
            y[mt][nt].z += bb.x + x1.x; y[mt][nt].w += bb.y + x1.y;
            s0 += y[mt][nt].x + y[mt][nt].y;  q0 += y[mt][nt].x * y[mt][nt].x + y[mt][nt].y * y[mt][nt].y;
            s1 += y[mt][nt].z + y[mt][nt].w;  q1 += y[mt][nt].z * y[mt][nt].z + y[mt][nt].w * y[mt][nt].w;
        }
        s0 += __shfl_xor_sync(0xffffffffu, s0, 1); s0 += __shfl_xor_sync(0xffffffffu, s0, 2);
        q0 += __shfl_xor_sync(0xffffffffu, q0, 1); q0 += __shfl_xor_sync(0xffffffffu, q0, 2);
        s1 += __shfl_xor_sync(0xffffffffu, s1, 1); s1 += __shfl_xor_sync(0xffffffffu, s1, 2);
        q1 += __shfl_xor_sync(0xffffffffu, q1, 1); q1 += __shfl_xor_sync(0xffffffffu, q1, 2);
        float mu0 = s0 * (1.f / 64.f), mu1 = s1 * (1.f / 64.f);
        float rs0 = rsqrtf(q0 * (1.f / 64.f) - mu0 * mu0 + 1e-5f);
        float rs1 = rsqrtf(q1 * (1.f / 64.f) - mu1 * mu1 + 1e-5f);
        #pragma unroll
        for (int nt = 0; nt < 8; nt++) {
            int c = 8 * nt + 2 * t;
            float2 gg = __ldg((const float2*)&lng[c]);
            float2 bb = __ldg((const float2*)&lnb[c]);
            *(float2*)&og[rA * 64 + c] = make_float2((y[mt][nt].x - mu0) * rs0 * gg.x + bb.x,
                                                     (y[mt][nt].y - mu0) * rs0 * gg.y + bb.y);
            *(float2*)&og[rB * 64 + c] = make_float2((y[mt][nt].z - mu1) * rs1 * gg.x + bb.x,
                                                     (y[mt][nt].w - mu1) * rs1 * gg.y + bb.y);
        }
    }
}

extern "C" void kernel_launch(void* const* d_in, const int* in_sizes, int n_in,
                              void* d_out, int out_size)
{
    const float* x   = (const float*)d_in[1];
    const float* Wq  = (const float*)d_in[2];
    const float* bq  = (const float*)d_in[3];
    const float* Wk  = (const float*)d_in[4];
    const float* bk  = (const float*)d_in[5];
    const float* Wv  = (const float*)d_in[6];
    const float* bv  = (const float*)d_in[7];
    const float* Wo  = (const float*)d_in[8];
    const float* bo  = (const float*)d_in[9];
    const float* lng = (const float*)d_in[10];
    const float* lnb = (const float*)d_in[11];
    float* out = (float*)d_out;

    int tiles = in_sizes[1] / (256 * 64);   // B*N = 1024
    size_t smem = (size_t)(256 * QS + 64 * VS + 4 * 64 * WS) * sizeof(__half); // 107520 B

    cudaFuncSetAttribute(pair_attn_v4,
                         cudaFuncAttributeMaxDynamicSharedMemorySize, (int)smem);

    pair_attn_v4<<<tiles, 256, smem>>>(x, Wq, bq, Wk, bk, Wv, bv, Wo, bo,
                                       lng, lnb, out);
}